// round 9
// baseline (speedup 1.0000x reference)
#include <cuda_runtime.h>
#include <math.h>

constexpr int B_  = 8;
constexpr int N_  = 512;
constexpr int M_  = 512;
constexpr int D_  = 512;
constexpr int ND_ = N_ + M_ - 1;   // 1023 anti-diagonals
constexpr float NEGL    = -1.0e9f;
constexpr float INV_LN2 = 1.44269504088896340736f;

// Diagonal-major scratch (zero-initialized; invalid slots are never written,
// so they stay zero — bwd relies on this for implicit masking).
__device__ float2 g_tha[(size_t)B_ * ND_ * N_];
__device__ float2 g_w  [(size_t)B_ * ND_ * N_];
__device__ float  g_e  [(size_t)B_ * ND_ * N_];

__device__ __forceinline__ float ex2f_(float x) { float y; asm("ex2.approx.ftz.f32 %0, %1;" : "=f"(y) : "f"(x)); return y; }
__device__ __forceinline__ float lg2f_(float x) { float y; asm("lg2.approx.f32 %0, %1;"     : "=f"(y) : "f"(x)); return y; }
__device__ __forceinline__ float rcpf_(float x) { float y; asm("rcp.approx.f32 %0, %1;"     : "=f"(y) : "f"(x)); return y; }

// ---------------------------------------------------------------------------
// GEMM + activation (unchanged): 128x128 tile, 256 thr, 8x8 micro.
// ---------------------------------------------------------------------------
__global__ void __launch_bounds__(256, 2) gemm_act_kernel(
    const float* __restrict__ zx, const float* __restrict__ zy,
    const float* __restrict__ gx, const float* __restrict__ gy,
    float* __restrict__ out)
{
    const int mz  = blockIdx.z;
    const int b   = mz & 7;
    const int sel = mz >> 3;
    const float* X = (sel ? gx : zx) + (size_t)b * N_ * D_;
    const float* Y = (sel ? gy : zy) + (size_t)b * M_ * D_;
    float* C = out + (size_t)(1 + sel) * B_ * N_ * M_ + (size_t)b * N_ * M_;

    const int row0 = blockIdx.y * 128;
    const int col0 = blockIdx.x * 128;

    __shared__ float Xs[16][132];
    __shared__ float Ys[16][132];

    const int t  = threadIdx.x;
    const int lr = t >> 1;
    const int lk = (t & 1) * 8;
    const int ty = t >> 4;
    const int tx = t & 15;

    float acc[8][8];
#pragma unroll
    for (int r = 0; r < 8; ++r)
#pragma unroll
        for (int c = 0; c < 8; ++c) acc[r][c] = 0.f;

    for (int k0 = 0; k0 < D_; k0 += 16) {
        const float4 xv0 = *(const float4*)(X + (size_t)(row0 + lr) * D_ + k0 + lk);
        const float4 xv1 = *(const float4*)(X + (size_t)(row0 + lr) * D_ + k0 + lk + 4);
        const float4 yv0 = *(const float4*)(Y + (size_t)(col0 + lr) * D_ + k0 + lk);
        const float4 yv1 = *(const float4*)(Y + (size_t)(col0 + lr) * D_ + k0 + lk + 4);
        __syncthreads();
        Xs[lk + 0][lr] = xv0.x; Xs[lk + 1][lr] = xv0.y; Xs[lk + 2][lr] = xv0.z; Xs[lk + 3][lr] = xv0.w;
        Xs[lk + 4][lr] = xv1.x; Xs[lk + 5][lr] = xv1.y; Xs[lk + 6][lr] = xv1.z; Xs[lk + 7][lr] = xv1.w;
        Ys[lk + 0][lr] = yv0.x; Ys[lk + 1][lr] = yv0.y; Ys[lk + 2][lr] = yv0.z; Ys[lk + 3][lr] = yv0.w;
        Ys[lk + 4][lr] = yv1.x; Ys[lk + 5][lr] = yv1.y; Ys[lk + 6][lr] = yv1.z; Ys[lk + 7][lr] = yv1.w;
        __syncthreads();
#pragma unroll
        for (int kk = 0; kk < 16; ++kk) {
            float a0[8], b0[8];
            *(float4*)(a0)     = *(const float4*)&Xs[kk][ty * 8];
            *(float4*)(a0 + 4) = *(const float4*)&Xs[kk][ty * 8 + 4];
            *(float4*)(b0)     = *(const float4*)&Ys[kk][tx * 8];
            *(float4*)(b0 + 4) = *(const float4*)&Ys[kk][tx * 8 + 4];
#pragma unroll
            for (int r = 0; r < 8; ++r)
#pragma unroll
                for (int c = 0; c < 8; ++c)
                    acc[r][c] = fmaf(a0[r], b0[c], acc[r][c]);
        }
    }

#pragma unroll
    for (int r = 0; r < 8; ++r) {
        const int row = row0 + ty * 8 + r;
#pragma unroll
        for (int c4 = 0; c4 < 8; c4 += 4) {
            float4 v;
            float* vp = &v.x;
#pragma unroll
            for (int q = 0; q < 4; ++q) {
                const float x = acc[r][c4 + q];
                const float l = log1pf(__expf(-fabsf(x)));
                vp[q] = sel ? (fminf(x, 0.f) - l)     // log_sigmoid
                            : (fmaxf(x, 0.f) + l);    // softplus
            }
            *(float4*)(C + (size_t)row * M_ + col0 + tx * 8 + c4) = v;
        }
    }
}

// ---------------------------------------------------------------------------
// Diagonalize: theta,A (row-major) -> g_tha (diag-major float2, pre-scaled).
// ---------------------------------------------------------------------------
__global__ void __launch_bounds__(256) diag_kernel(const float* __restrict__ out)
{
    const float* theta = out + (size_t)B_ * N_ * M_;
    const float* Ag    = out + (size_t)2 * B_ * N_ * M_;
    const int b  = blockIdx.z;
    const int i0 = blockIdx.y * 32;
    const int j0 = blockIdx.x * 32;

    __shared__ float sth[32 * 32];
    __shared__ float sa [32 * 32];

    const int t    = threadIdx.x;
    const int warp = t >> 5;
    const int lane = t & 31;

#pragma unroll
    for (int it = 0; it < 4; ++it) {
        const int r = warp + it * 8;
        const int c = lane;
        const size_t g = ((size_t)b * N_ + (i0 + r)) * M_ + (j0 + c);
        sth[r * 32 + c] = theta[g] * INV_LN2;
        sa [r * 32 + c] = Ag[g]    * INV_LN2;
    }
    __syncthreads();

    float2* dst = g_tha + (size_t)b * ND_ * N_;
#pragma unroll
    for (int dd0 = 0; dd0 < 64; dd0 += 8) {
        const int dd = dd0 + warp;
        const int il = lane;
        const int jl = dd - il;
        if ((unsigned)jl < 32u) {
            const int d = i0 + j0 + dd;
            dst[(size_t)d * N_ + (i0 + il)] = make_float2(sth[il * 32 + jl], sa[il * 32 + jl]);
        }
    }
}

// ---------------------------------------------------------------------------
// Undiagonalize: g_e (diag-major) -> aln (row-major).
// ---------------------------------------------------------------------------
__global__ void __launch_bounds__(256) undiag_kernel(float* __restrict__ out)
{
    const int b  = blockIdx.z;
    const int i0 = blockIdx.y * 32;
    const int j0 = blockIdx.x * 32;

    __shared__ float se[32 * 32];

    const int t    = threadIdx.x;
    const int warp = t >> 5;
    const int lane = t & 31;

    const float* src = g_e + (size_t)b * ND_ * N_;
#pragma unroll
    for (int dd0 = 0; dd0 < 64; dd0 += 8) {
        const int dd = dd0 + warp;
        const int il = lane;
        const int jl = dd - il;
        if ((unsigned)jl < 32u) {
            const int d = i0 + j0 + dd;
            se[il * 32 + jl] = src[(size_t)d * N_ + (i0 + il)];
        }
    }
    __syncthreads();

    float* alnB = out + (size_t)b * N_ * M_;
#pragma unroll
    for (int it = 0; it < 4; ++it) {
        const int r = warp + it * 8;
        const int c = lane;
        alnB[(size_t)(i0 + r) * M_ + (j0 + c)] = se[r * 32 + c];
    }
}

// ---------------------------------------------------------------------------
// Forward soft-NW: 2 rows/thread tile wavefront. 256 threads, 8 warps; warp w
// owns rows [64w, 64w+64). All cell operands are previous-step registers; the
// cross-row shuffle is consumed one step after issue (off-chain). Wave t:
// warp w runs chunk c = t - 3w, c in [0,18); 39 waves.
// ---------------------------------------------------------------------------
__global__ void __launch_bounds__(256) nw_fwd_kernel()
{
    const int b    = blockIdx.x;
    const int tid  = threadIdx.x;
    const int wid  = tid >> 5;
    const int lane = tid & 31;
    const int r0   = 2 * tid;
    const int r1   = r0 + 1;
    const int wrow = wid * 64;     // warp's first row

    __shared__ float ring[9][128];   // row 8 never written: NEGL boundary
    for (int i = tid; i < 9 * 128; i += 256) ((float*)ring)[i] = NEGL;
    __syncthreads();

    const float4* THA4 = (const float4*)(g_tha + (size_t)b * ND_ * N_);  // [d*256 + tid]
    float2*       Wb   = g_w + (size_t)b * ND_ * N_;

    float*       ringWr = ring[wid];
    const float* ringRd = ring[wid == 0 ? 8 : wid - 1];

    // depth-8 queue of (th0, A0, th1, A1) for rows r0, r1
    float4 q[8];
#pragma unroll
    for (int k = 0; k < 8; ++k) q[k] = THA4[(size_t)(wrow + k) * 256 + tid];

    float vp0 = NEGL, vp1 = NEGL, vp0_old = NEGL;
    float nbPrev = (tid == 0) ? 0.f : NEGL;   // V[r0-1, d-2]; seeds V[0,0]=0

    for (int t = 0; t < 39; ++t) {
        const int c = t - 3 * wid;
        if (c >= 0 && c < 18) {
            const int d0 = wrow + 32 * c;
#pragma unroll
            for (int s = 0; s < 32; ++s) {
                const int d = d0 + s;
                const float4 ta = q[s & 7];
                int dp = d + 8; dp = dp > ND_ - 1 ? ND_ - 1 : dp;
                q[s & 7] = THA4[(size_t)dp * 256 + tid];

                const float ringv = ringRd[(d - 1) & 127];     // broadcast LDS
                float nb = __shfl_up_sync(0xffffffffu, vp1, 1);
                nb = (lane == 0) ? ringv : nb;                 // V[r0-1, d-1]

                // cell r0: up = nb, left = vp0, diag = nbPrev
                const float x0a = ta.y + nb;
                const float x2a = ta.y + vp0;
                const float ma  = fmaxf(fmaxf(x0a, x2a), nbPrev);
                const float e0a = ex2f_(x0a - ma);
                const float e1a = ex2f_(nbPrev - ma);
                const float e2a = ex2f_(x2a - ma);
                const float sa  = e0a + e1a + e2a;
                const float ra  = rcpf_(sa);
                const float v0  = ta.x + ma + lg2f_(sa);

                // cell r1: up = vp0 (pre-update), left = vp1, diag = vp0_old
                const float x0b = ta.w + vp0;
                const float x2b = ta.w + vp1;
                const float mb  = fmaxf(fmaxf(x0b, x2b), vp0_old);
                const float e0b = ex2f_(x0b - mb);
                const float e1b = ex2f_(vp0_old - mb);
                const float e2b = ex2f_(x2b - mb);
                const float sb  = e0b + e1b + e2b;
                const float rb  = rcpf_(sb);
                const float v1  = ta.z + mb + lg2f_(sb);

                const bool a0 = (unsigned)(d - r0) < (unsigned)M_;
                const bool a1 = (unsigned)(d - r1) < (unsigned)M_;
                float4 wst;
                wst.x = a0 ? e0a * ra : 0.f;   // wU(r0)
                wst.y = a0 ? e2a * ra : 0.f;   // wL(r0)
                wst.z = a1 ? e0b * rb : 0.f;   // wU(r1)
                wst.w = a1 ? e2b * rb : 0.f;   // wL(r1)
                if (a0 | a1) *(float4*)&Wb[(size_t)d * N_ + r0] = wst;

                nbPrev  = nb;
                vp0_old = vp0;
                vp0 = a0 ? v0 : vp0;
                vp1 = a1 ? v1 : vp1;
                if (lane == 31) ringWr[d & 127] = vp1;         // @p STS.32
            }
        }
        __syncthreads();
    }
}

// ---------------------------------------------------------------------------
// Backward soft-NW: 2 rows/thread, mirrored wavefront. All weights come from
// off-chain gmem streams: own rows (float4/diag) + row r2 (float2/diag).
// Chain per step is just the FMA trees. Wave t: warp w runs chunk
// cc = t - 3*(7-w); 39 waves.
//   E[i,j] = E[i+1,j]*wU(i+1,j) + E[i,j+1]*wL(i,j+1) + E[i+1,j+1]*wD(i+1,j+1)
// ---------------------------------------------------------------------------
__global__ void __launch_bounds__(256) nw_bwd_kernel()
{
    const int b    = blockIdx.x;
    const int tid  = threadIdx.x;
    const int wid  = tid >> 5;
    const int lane = tid & 31;
    const int r0   = 2 * tid;
    const int r1   = r0 + 1;
    const int r2   = r0 + 2;
    const bool hasN = (r2 < N_);
    const int dTop = 64 * wid + 574;

    __shared__ float ring[9][128];   // row 8 never written: zero boundary
    for (int i = tid; i < 9 * 128; i += 256) ((float*)ring)[i] = 0.f;
    __syncthreads();

    const float2* Wb  = g_w + (size_t)b * ND_ * N_;
    const float4* Wb4 = (const float4*)Wb;            // [d*256 + tid] = rows r0,r1
    float*        Eb  = g_e + (size_t)b * ND_ * N_;

    float*       ringWr = ring[wid];
    const float* ringRd = ring[wid == 7 ? 8 : wid + 1];

    const float2 zero2 = make_float2(0.f, 0.f);
    const float4 zero4 = make_float4(0.f, 0.f, 0.f, 0.f);

    // depth-8 queues: slot k holds W[dTop+1-k] initially (descending stream).
    float4 qO[8];   // W[dd][r0], W[dd][r1]
    float2 qN[8];   // W[dd][r2]
#pragma unroll
    for (int k = 0; k < 8; ++k) {
        const int dd = dTop + 1 - k;
        const bool ok = dd <= ND_ - 1;
        const int ddc = ok ? dd : ND_ - 1;
        qO[k] = ok ? Wb4[(size_t)ddc * 256 + tid] : zero4;
        qN[k] = (ok && hasN) ? Wb[(size_t)ddc * N_ + r2] : zero2;
    }
    // prev registers: W[dTop+2]
    float4 pO = zero4;
    float2 pN = zero2;
    {
        const int dd = dTop + 2;
        if (dd <= ND_ - 1) {
            pO = Wb4[(size_t)dd * 256 + tid];
            if (hasN) pN = Wb[(size_t)dd * N_ + r2];
        }
    }

    float ep0 = 0.f, ep1 = 0.f, ep1_old = 0.f;   // E[r0,d+1], E[r1,d+1], E[r1,d+2]
    float nbE_old = 0.f;                          // E[r2, d+2]

    for (int t = 0; t < 39; ++t) {
        const int cc = t - 3 * (7 - wid);
        if (cc >= 0 && cc < 18) {
            const int d0 = dTop - 32 * cc;
#pragma unroll
            for (int s = 0; s < 32; ++s) {
                const int d = d0 - s;
                const float4 cO = qO[s & 7];     // W[d+1][r0], W[d+1][r1]
                const float2 cN = qN[s & 7];     // W[d+1][r2]
                int dd = d - 7; dd = dd < 0 ? 0 : dd;
                qO[s & 7] = Wb4[(size_t)dd * 256 + tid];
                qN[s & 7] = hasN ? Wb[(size_t)dd * N_ + r2] : zero2;

                const float rv = ringRd[(d + 1) & 127];        // broadcast LDS
                float nbE = __shfl_down_sync(0xffffffffu, ep0, 1);
                nbE = (lane == 31) ? rv : nbE;                 // E[r2, d+1]

                // cell r0: children (r1,d+1), (r0,d+1), (r1,d+2)
                float e0 = ep1 * cO.z + ep0 * cO.y
                         + ep1_old * (1.f - pO.z - pO.w);
                // cell r1: children (r2,d+1), (r1,d+1), (r2,d+2)
                float e1 = nbE * cN.x + ep1 * cO.w
                         + nbE_old * (1.f - pN.x - pN.y);
                e1 = (d == 1022 && r1 == 511) ? 1.f : e1;      // base case E[N,M]

                const bool a0 = (unsigned)(d - r0) < (unsigned)M_;
                const bool a1 = (unsigned)(d - r1) < (unsigned)M_;
                float2 est;
                est.x = a0 ? e0 : 0.f;
                est.y = a1 ? e1 : 0.f;
                if (a0 | a1) *(float2*)&Eb[(size_t)d * N_ + r0] = est;

                ep1_old = ep1;
                nbE_old = nbE;
                ep0 = a0 ? e0 : ep0;
                ep1 = a1 ? e1 : ep1;
                pO = cO; pN = cN;
                if (lane == 0) ringWr[d & 127] = ep0;          // @p STS.32
            }
        }
        __syncthreads();
    }
}

// ---------------------------------------------------------------------------
// launch
// ---------------------------------------------------------------------------
extern "C" void kernel_launch(void* const* d_in, const int* in_sizes, int n_in,
                              void* d_out, int out_size)
{
    const float* zx = (const float*)d_in[0];
    const float* zy = (const float*)d_in[1];
    const float* gx = (const float*)d_in[2];
    const float* gy = (const float*)d_in[3];
    float* out = (float*)d_out;   // [aln | theta | A]

    dim3 ggrid(M_ / 128, N_ / 128, 2 * B_);
    gemm_act_kernel<<<ggrid, 256>>>(zx, zy, gx, gy, out);

    dim3 tgrid(M_ / 32, N_ / 32, B_);
    diag_kernel<<<tgrid, 256>>>(out);
    nw_fwd_kernel<<<B_, 256>>>();
    nw_bwd_kernel<<<B_, 256>>>();
    undiag_kernel<<<tgrid, 256>>>(out);
}

// round 10
// speedup vs baseline: 1.2104x; 1.2104x over previous
#include <cuda_runtime.h>
#include <math.h>

constexpr int B_  = 8;
constexpr int N_  = 512;
constexpr int M_  = 512;
constexpr int D_  = 512;
constexpr int ND_ = N_ + M_ - 1;   // 1023 anti-diagonals
constexpr float NEGL    = -1.0e9f;
constexpr float INV_LN2 = 1.44269504088896340736f;

// Diagonal-major scratch (zero-initialized; invalid slots are never written,
// so they stay zero — bwd relies on this for implicit masking).
__device__ float2 g_tha[(size_t)B_ * ND_ * N_];
__device__ float2 g_w  [(size_t)B_ * ND_ * N_];
__device__ float  g_e  [(size_t)B_ * ND_ * N_];

__device__ __forceinline__ float ex2f_(float x) { float y; asm("ex2.approx.ftz.f32 %0, %1;" : "=f"(y) : "f"(x)); return y; }
__device__ __forceinline__ float lg2f_(float x) { float y; asm("lg2.approx.f32 %0, %1;"     : "=f"(y) : "f"(x)); return y; }
__device__ __forceinline__ float rcpf_(float x) { float y; asm("rcp.approx.f32 %0, %1;"     : "=f"(y) : "f"(x)); return y; }

__device__ __forceinline__ unsigned tf32_(float x) {
    unsigned y; asm("cvt.rna.tf32.f32 %0, %1;" : "=r"(y) : "f"(x)); return y;
}
__device__ __forceinline__ void mma_tf32(float* c, const unsigned* a, const unsigned* b) {
    asm volatile(
        "mma.sync.aligned.m16n8k8.row.col.f32.tf32.tf32.f32 "
        "{%0,%1,%2,%3}, {%4,%5,%6,%7}, {%8,%9}, {%0,%1,%2,%3};"
        : "+f"(c[0]), "+f"(c[1]), "+f"(c[2]), "+f"(c[3])
        : "r"(a[0]), "r"(a[1]), "r"(a[2]), "r"(a[3]), "r"(b[0]), "r"(b[1]));
}

// ---------------------------------------------------------------------------
// GEMM + activation via 3xTF32 tensor-core mma.
// 128x128 block tile, 256 threads, 8 warps in 4(m)x2(n); warp tile 32x64.
// K-chunk 16 staged in smem as tf32 big/small planes.
// Permuted k layout within a chunk: pos = ks + 2*(k&3) + ((k>>2)&1), ks = 8*(k>>3),
// so (k, k+4) are adjacent -> every fragment load is one LDS.64.
// Row pitch 24 floats -> conflict-free for the m16n8k8 lane pattern.
// ---------------------------------------------------------------------------
constexpr int GP_ = 24;   // smem row pitch (floats) per 16-value k-chunk row

__global__ void __launch_bounds__(256, 2) gemm_act_kernel(
    const float* __restrict__ zx, const float* __restrict__ zy,
    const float* __restrict__ gx, const float* __restrict__ gy,
    float* __restrict__ out)
{
    const int mz  = blockIdx.z;
    const int b   = mz & 7;
    const int sel = mz >> 3;
    const float* X = (sel ? gx : zx) + (size_t)b * N_ * D_;
    const float* Y = (sel ? gy : zy) + (size_t)b * M_ * D_;
    float* C = out + (size_t)(1 + sel) * B_ * N_ * M_ + (size_t)b * N_ * M_;

    const int row0 = blockIdx.y * 128;
    const int col0 = blockIdx.x * 128;

    __shared__ float Xb[128 * GP_], Xs[128 * GP_];
    __shared__ float Yb[128 * GP_], Ys[128 * GP_];

    const int t    = threadIdx.x;
    const int lane = t & 31;
    const int wid  = t >> 5;
    const int wm   = wid & 3;        // warp row block (32 rows)
    const int wn   = wid >> 2;       // warp col block (64 cols)
    const int lr   = t >> 1;         // 0..127: row to load
    const int lk   = (t & 1) * 8;    // 0 or 8: k offset to load

    const int qr  = lane >> 2;       // fragment row within 8
    const int qc2 = (lane & 3) * 2;  // fragment k-pair position

    float acc[2][8][4];
#pragma unroll
    for (int mt = 0; mt < 2; ++mt)
#pragma unroll
        for (int nt = 0; nt < 8; ++nt)
#pragma unroll
            for (int q = 0; q < 4; ++q) acc[mt][nt][q] = 0.f;

    for (int k0 = 0; k0 < D_; k0 += 16) {
        const float4 xv0 = *(const float4*)(X + (size_t)(row0 + lr) * D_ + k0 + lk);
        const float4 xv1 = *(const float4*)(X + (size_t)(row0 + lr) * D_ + k0 + lk + 4);
        const float4 yv0 = *(const float4*)(Y + (size_t)(col0 + lr) * D_ + k0 + lk);
        const float4 yv1 = *(const float4*)(Y + (size_t)(col0 + lr) * D_ + k0 + lk + 4);
        __syncthreads();
        {
            float* xb = Xb + lr * GP_ + lk;
            float* xs = Xs + lr * GP_ + lk;
            float* yb = Yb + lr * GP_ + lk;
            float* ys = Ys + lr * GP_ + lk;
            const float xv[8] = { xv0.x, xv0.y, xv0.z, xv0.w, xv1.x, xv1.y, xv1.z, xv1.w };
            const float yv[8] = { yv0.x, yv0.y, yv0.z, yv0.w, yv1.x, yv1.y, yv1.z, yv1.w };
#pragma unroll
            for (int k = 0; k < 8; ++k) {
                const int pos = 2 * (k & 3) + (k >> 2);   // perm within 8, par bit from k>=4
                const float bx = __uint_as_float(tf32_(xv[k]));
                xb[pos] = bx;
                xs[pos] = __uint_as_float(tf32_(xv[k] - bx));
                const float by = __uint_as_float(tf32_(yv[k]));
                yb[pos] = by;
                ys[pos] = __uint_as_float(tf32_(yv[k] - by));
            }
        }
        __syncthreads();

#pragma unroll
        for (int ks = 0; ks < 16; ks += 8) {
            unsigned Ab[2][4], As[2][4];
#pragma unroll
            for (int mt = 0; mt < 2; ++mt) {
                const int arow = 32 * wm + 16 * mt;
                const float2 pb0 = *(const float2*)&Xb[(arow + qr) * GP_ + ks + qc2];
                const float2 pb1 = *(const float2*)&Xb[(arow + 8 + qr) * GP_ + ks + qc2];
                Ab[mt][0] = __float_as_uint(pb0.x); Ab[mt][2] = __float_as_uint(pb0.y);
                Ab[mt][1] = __float_as_uint(pb1.x); Ab[mt][3] = __float_as_uint(pb1.y);
                const float2 ps0 = *(const float2*)&Xs[(arow + qr) * GP_ + ks + qc2];
                const float2 ps1 = *(const float2*)&Xs[(arow + 8 + qr) * GP_ + ks + qc2];
                As[mt][0] = __float_as_uint(ps0.x); As[mt][2] = __float_as_uint(ps0.y);
                As[mt][1] = __float_as_uint(ps1.x); As[mt][3] = __float_as_uint(ps1.y);
            }
#pragma unroll
            for (int nt = 0; nt < 8; ++nt) {
                const int ncol = 64 * wn + 8 * nt;
                const float2 bb = *(const float2*)&Yb[(ncol + qr) * GP_ + ks + qc2];
                const float2 bs = *(const float2*)&Ys[(ncol + qr) * GP_ + ks + qc2];
                unsigned Bb[2] = { __float_as_uint(bb.x), __float_as_uint(bb.y) };
                unsigned Bs[2] = { __float_as_uint(bs.x), __float_as_uint(bs.y) };
#pragma unroll
                for (int mt = 0; mt < 2; ++mt) {
                    mma_tf32(acc[mt][nt], Ab[mt], Bb);
                    mma_tf32(acc[mt][nt], Ab[mt], Bs);
                    mma_tf32(acc[mt][nt], As[mt], Bb);
                }
            }
        }
    }

    // epilogue + activation
#pragma unroll
    for (int mt = 0; mt < 2; ++mt) {
#pragma unroll
        for (int nt = 0; nt < 8; ++nt) {
            const int row = row0 + 32 * wm + 16 * mt + qr;
            const int col = col0 + 64 * wn + 8 * nt + qc2;
            float v[4];
#pragma unroll
            for (int q = 0; q < 4; ++q) {
                const float x = acc[mt][nt][q];
                const float l = log1pf(__expf(-fabsf(x)));
                v[q] = sel ? (fminf(x, 0.f) - l)     // log_sigmoid
                           : (fmaxf(x, 0.f) + l);    // softplus
            }
            *(float2*)(C + (size_t)row * M_ + col)       = make_float2(v[0], v[1]);
            *(float2*)(C + (size_t)(row + 8) * M_ + col) = make_float2(v[2], v[3]);
        }
    }
}

// ---------------------------------------------------------------------------
// Diagonalize: theta,A (row-major) -> g_tha (diag-major float2, pre-scaled).
// ---------------------------------------------------------------------------
__global__ void __launch_bounds__(256) diag_kernel(const float* __restrict__ out)
{
    const float* theta = out + (size_t)B_ * N_ * M_;
    const float* Ag    = out + (size_t)2 * B_ * N_ * M_;
    const int b  = blockIdx.z;
    const int i0 = blockIdx.y * 32;
    const int j0 = blockIdx.x * 32;

    __shared__ float sth[32 * 32];
    __shared__ float sa [32 * 32];

    const int t    = threadIdx.x;
    const int warp = t >> 5;
    const int lane = t & 31;

#pragma unroll
    for (int it = 0; it < 4; ++it) {
        const int r = warp + it * 8;
        const int c = lane;
        const size_t g = ((size_t)b * N_ + (i0 + r)) * M_ + (j0 + c);
        sth[r * 32 + c] = theta[g] * INV_LN2;
        sa [r * 32 + c] = Ag[g]    * INV_LN2;
    }
    __syncthreads();

    float2* dst = g_tha + (size_t)b * ND_ * N_;
#pragma unroll
    for (int dd0 = 0; dd0 < 64; dd0 += 8) {
        const int dd = dd0 + warp;
        const int il = lane;
        const int jl = dd - il;
        if ((unsigned)jl < 32u) {
            const int d = i0 + j0 + dd;
            dst[(size_t)d * N_ + (i0 + il)] = make_float2(sth[il * 32 + jl], sa[il * 32 + jl]);
        }
    }
}

// ---------------------------------------------------------------------------
// Undiagonalize: g_e (diag-major) -> aln (row-major).
// ---------------------------------------------------------------------------
__global__ void __launch_bounds__(256) undiag_kernel(float* __restrict__ out)
{
    const int b  = blockIdx.z;
    const int i0 = blockIdx.y * 32;
    const int j0 = blockIdx.x * 32;

    __shared__ float se[32 * 32];

    const int t    = threadIdx.x;
    const int warp = t >> 5;
    const int lane = t & 31;

    const float* src = g_e + (size_t)b * ND_ * N_;
#pragma unroll
    for (int dd0 = 0; dd0 < 64; dd0 += 8) {
        const int dd = dd0 + warp;
        const int il = lane;
        const int jl = dd - il;
        if ((unsigned)jl < 32u) {
            const int d = i0 + j0 + dd;
            se[il * 32 + jl] = src[(size_t)d * N_ + (i0 + il)];
        }
    }
    __syncthreads();

    float* alnB = out + (size_t)b * N_ * M_;
#pragma unroll
    for (int it = 0; it < 4; ++it) {
        const int r = warp + it * 8;
        const int c = lane;
        alnB[(size_t)(i0 + r) * M_ + (j0 + c)] = se[r * 32 + c];
    }
}

// ---------------------------------------------------------------------------
// Forward soft-NW (R7 config): tile wavefront, branchless step body,
// depth-16 prefetch of (theta, A).
// ---------------------------------------------------------------------------
__global__ void __launch_bounds__(512) nw_fwd_kernel()
{
    const int b    = blockIdx.x;
    const int tid  = threadIdx.x;
    const int wid  = tid >> 5;
    const int lane = tid & 31;
    const int r    = tid;
    const int w0   = wid * 32;

    __shared__ float bndV[17][128];   // row 16 never written: NEGL boundary
    for (int i = tid; i < 17 * 128; i += 512) ((float*)bndV)[i] = NEGL;
    __syncthreads();

    const float2* THA = g_tha + (size_t)b * ND_ * N_;
    float2*       Wb  = g_w   + (size_t)b * ND_ * N_;

    float*       ringWr = bndV[wid];
    const float* ringRd = bndV[wid == 0 ? 16 : wid - 1];

    float2 th[16];
#pragma unroll
    for (int q = 0; q < 16; ++q) th[q] = THA[(size_t)(w0 + q) * N_ + r];

    float vp     = NEGL;
    float nbPrev = (tid == 0) ? 0.f : NEGL;   // seeds V[0,0] = 0 for cell (0,0)

    for (int t = 0; t < 47; ++t) {
        const int c = t - 2 * wid;
        if (c >= 0 && c < 17) {
            const int d0 = w0 + 32 * c;
#pragma unroll
            for (int s = 0; s < 32; ++s) {
                const int d = d0 + s;
                const float2 ta = th[s & 15];
                int dp = d + 16; dp = dp > ND_ - 1 ? ND_ - 1 : dp;
                th[s & 15] = THA[(size_t)dp * N_ + r];

                const float ringv = ringRd[(d - 1) & 127];     // broadcast LDS
                float nb = __shfl_up_sync(0xffffffffu, vp, 1);
                nb = (lane == 0) ? ringv : nb;

                const float x0 = ta.y + nb;        // A + V[i-1, j]
                const float x2 = ta.y + vp;        // A + V[i,   j-1]
                const float dg = nbPrev;           //     V[i-1, j-1]
                const float m  = fmaxf(fmaxf(x0, x2), dg);
                const float e0 = ex2f_(x0 - m);
                const float e1 = ex2f_(dg - m);
                const float e2 = ex2f_(x2 - m);
                const float ss = e0 + e1 + e2;
                const float rr = rcpf_(ss);
                const float v  = ta.x + m + lg2f_(ss);

                const bool active = (unsigned)(d - r) < (unsigned)M_;
                if (active) Wb[(size_t)d * N_ + r] = make_float2(e0 * rr, e2 * rr);
                vp = active ? v : vp;
                nbPrev = nb;
                if (lane == 31) ringWr[d & 127] = vp;          // @p STS.32
            }
        }
        __syncthreads();
    }
}

// ---------------------------------------------------------------------------
// Backward soft-NW (R7 config): off-chain weights via two depth-16 diag-major
// register streams (rows r and r+1); serial chain = shfl(E) -> FMA -> SEL.
//   E[i,j] = E[i+1,j]*wU(i+1,j) + E[i,j+1]*wL(i,j+1) + E[i+1,j+1]*wD(i+1,j+1)
// ---------------------------------------------------------------------------
__global__ void __launch_bounds__(512) nw_bwd_kernel()
{
    const int b    = blockIdx.x;
    const int tid  = threadIdx.x;
    const int wid  = tid >> 5;
    const int lane = tid & 31;
    const int r    = tid;
    const int w0   = wid * 32;
    const int dTop = w0 + 542;
    const bool hasNext = (r + 1 < N_);   // row r+1 exists

    __shared__ float eRing[17][128];     // row 16 never written: zero boundary
    for (int i = tid; i < 17 * 128; i += 512) ((float*)eRing)[i] = 0.f;
    __syncthreads();

    const float2* Wb = g_w + (size_t)b * ND_ * N_;
    float*        Eb = g_e + (size_t)b * ND_ * N_;

    float*       ringWr = eRing[wid];
    const float* ringRd = eRing[wid + 1];   // warp 15 -> row 16 (zeros)

    const float2 zero2 = make_float2(0.f, 0.f);

    float2 qA[16], qB[16];
#pragma unroll
    for (int q = 0; q < 16; ++q) {
        const int dd = dTop + 1 - q;
        const bool ok = (dd <= ND_ - 1);
        qA[q] = ok ? Wb[(size_t)dd * N_ + r] : zero2;
        qB[q] = (ok && hasNext) ? Wb[(size_t)dd * N_ + r + 1] : zero2;
    }

    float2 bPrev = zero2;
    {
        const int dd = dTop + 2;
        if (dd <= ND_ - 1 && hasNext) bPrev = Wb[(size_t)dd * N_ + r + 1];
    }

    float ep      = 0.f;   // my E at d+1
    float nbEPrev = 0.f;   // neighbor E at d+2

    for (int t = 0; t < 47; ++t) {
        const int cc = t - 2 * (15 - wid);
        if (cc >= 0 && cc < 17) {
            const int d0 = dTop - 32 * cc;
#pragma unroll
            for (int s = 0; s < 32; ++s) {
                const int d = d0 - s;
                const float2 cA = qA[s & 15];    // W[d+1][r]
                const float2 cB = qB[s & 15];    // W[d+1][r+1]
                int dd = d - 15; dd = dd < 0 ? 0 : dd;
                qA[s & 15] = Wb[(size_t)dd * N_ + r];
                qB[s & 15] = hasNext ? Wb[(size_t)dd * N_ + r + 1] : zero2;

                const float rv = ringRd[(d + 1) & 127];     // broadcast LDS
                float nbE = __shfl_down_sync(0xffffffffu, ep, 1);
                nbE = (lane == 31) ? rv : nbE;

                float e = nbE * cB.x                          // E[i+1,j]   * wU
                        + ep  * cA.y                          // E[i,j+1]   * wL
                        + nbEPrev * (1.f - bPrev.x - bPrev.y);// E[i+1,j+1] * wD
                e = (d == 1022 && r == 511) ? 1.f : e;        // base case E[N,M]

                const bool active = (unsigned)(d - r) < (unsigned)M_;
                const float ev = active ? e : 0.f;
                Eb[(size_t)d * N_ + r] = ev;                  // unconditional STG
                ep = active ? e : ep;
                nbEPrev = nbE;
                bPrev = cB;
                if (lane == 0) ringWr[d & 127] = ep;          // @p STS.32
            }
        }
        __syncthreads();
    }
}

// ---------------------------------------------------------------------------
// launch
// ---------------------------------------------------------------------------
extern "C" void kernel_launch(void* const* d_in, const int* in_sizes, int n_in,
                              void* d_out, int out_size)
{
    const float* zx = (const float*)d_in[0];
    const float* zy = (const float*)d_in[1];
    const float* gx = (const float*)d_in[2];
    const float* gy = (const float*)d_in[3];
    float* out = (float*)d_out;   // [aln | theta | A]

    dim3 ggrid(M_ / 128, N_ / 128, 2 * B_);
    gemm_act_kernel<<<ggrid, 256>>>(zx, zy, gx, gy, out);

    dim3 tgrid(M_ / 32, N_ / 32, B_);
    diag_kernel<<<tgrid, 256>>>(out);
    nw_fwd_kernel<<<B_, 512>>>();
    nw_bwd_kernel<<<B_, 512>>>();
    undiag_kernel<<<tgrid, 256>>>(out);
}